// round 14
// baseline (speedup 1.0000x reference)
#include <cuda_runtime.h>
#include <cstdint>

// VectorQuantization: N=32768, K=8192, D=256 (hardcoded; reference-pinned).
// argmin_j ||x_i - c_j||^2 via d = (x2_i + c2_j) - 2 * (x_i . c_j).
//
// KEY FIX (round 13 diagnosis): the output buffer is FLOAT32, not int32.
// All previous rounds wrote int32 bit patterns -> read back as float
// denormals ~1e-41 ~= 0 -> rel_err = ||ref||/||ref|| = 1.000000 exactly,
// regardless of kernel correctness. We now store (float)index.
//
// Core: 256 threads, 4x4 register tile, double-buffered 64x32 tiles,
// c2 accumulated inline from B tiles, x2 per row in smem, lexicographic
// (d, col) argmin == argmin first-index tie semantics.

#define VQ_N 32768
#define VQ_K 8192
#define D_DIM 256
#define BM 64
#define BN 64
#define BK 32
#define NTHREADS 256
#define FLT_BIG 3.402823466e38f

__global__ void __launch_bounds__(NTHREADS)
vq_tiled(const float* __restrict__ x, const float* __restrict__ vectors,
         float* __restrict__ out) {
    __shared__ __align__(16) float As[2][BK][BM];
    __shared__ __align__(16) float Bs[2][BK][BN];
    __shared__ float x2s[BM];
    __shared__ float redD[BM][16];
    __shared__ int   redI[BM][16];

    const int tid = threadIdx.x;
    const int tx = tid & 15;          // column group 0..15
    const int ty = tid >> 4;          // row group 0..15
    const int r0 = blockIdx.x * BM;

    const int lr  = tid & 63;         // loader row 0..63
    const int lkq = tid >> 6;         // loader k-quad group 0..3

    // ---- x2 per row (threads 0..63), straight from gmem ---------------------
    if (tid < BM) {
        const float* xr = x + (size_t)(r0 + tid) * D_DIM;
        float s = 0.f;
        #pragma unroll 8
        for (int k = 0; k < D_DIM; k++) s = fmaf(xr[k], xr[k], s);
        x2s[tid] = s;
    }

    // ---- prologue: (chunk 0, kc 0) into buffer 0 ----------------------------
    {
        const float* ax = x + (size_t)(r0 + lr) * D_DIM;
        const float* bv = vectors + (size_t)lr * D_DIM;
        #pragma unroll
        for (int i = 0; i < 2; i++) {
            int q = lkq + 4 * i;      // k-quad 0..7 (covers k 0..31)
            float4 a = *reinterpret_cast<const float4*>(ax + q * 4);
            float4 b = *reinterpret_cast<const float4*>(bv + q * 4);
            As[0][q * 4 + 0][lr] = a.x;  As[0][q * 4 + 1][lr] = a.y;
            As[0][q * 4 + 2][lr] = a.z;  As[0][q * 4 + 3][lr] = a.w;
            Bs[0][q * 4 + 0][lr] = b.x;  Bs[0][q * 4 + 1][lr] = b.y;
            Bs[0][q * 4 + 2][lr] = b.z;  Bs[0][q * 4 + 3][lr] = b.w;
        }
    }
    __syncthreads();   // publishes buffer 0 and x2s

    float bestd[4];
    int   besti[4];
    #pragma unroll
    for (int i = 0; i < 4; i++) { bestd[i] = FLT_BIG; besti[i] = 0; }

    const int nchunks = VQ_K / BN;    // 128
    const int nkc     = D_DIM / BK;   // 8
    int buf = 0;

    for (int chunk = 0; chunk < nchunks; chunk++) {
        const int n0 = chunk * BN;
        float acc[4][4];
        float c2x[4];
        #pragma unroll
        for (int i = 0; i < 4; i++) {
            c2x[i] = 0.f;
            #pragma unroll
            for (int j = 0; j < 4; j++) acc[i][j] = 0.f;
        }

        for (int kc = 0; kc < nkc; kc++) {
            const bool has_next = (kc < nkc - 1) || (chunk < nchunks - 1);
            float4 pfa[2], pfb[2];

            // register prefetch of next 64x32 tiles (hidden under compute)
            if (has_next) {
                const int nc = (kc < nkc - 1) ? chunk : chunk + 1;
                const int nk = (kc < nkc - 1) ? kc + 1 : 0;
                const float* ax = x + (size_t)(r0 + lr) * D_DIM + nk * BK;
                const float* bv = vectors + (size_t)(nc * BN + lr) * D_DIM + nk * BK;
                #pragma unroll
                for (int i = 0; i < 2; i++) {
                    int q = lkq + 4 * i;
                    pfa[i] = *reinterpret_cast<const float4*>(ax + q * 4);
                    pfb[i] = *reinterpret_cast<const float4*>(bv + q * 4);
                }
            }

            // 32 k-steps on current buffer: 16 dot FMAs + 4 c2 FMAs per k
            #pragma unroll 16
            for (int k = 0; k < BK; k++) {
                float4 av = *reinterpret_cast<const float4*>(&As[buf][k][ty * 4]);
                float b0 = Bs[buf][k][tx];
                float b1 = Bs[buf][k][tx + 16];
                float b2 = Bs[buf][k][tx + 32];
                float b3 = Bs[buf][k][tx + 48];
                c2x[0] = fmaf(b0, b0, c2x[0]);
                c2x[1] = fmaf(b1, b1, c2x[1]);
                c2x[2] = fmaf(b2, b2, c2x[2]);
                c2x[3] = fmaf(b3, b3, c2x[3]);
                acc[0][0] = fmaf(av.x, b0, acc[0][0]);
                acc[0][1] = fmaf(av.x, b1, acc[0][1]);
                acc[0][2] = fmaf(av.x, b2, acc[0][2]);
                acc[0][3] = fmaf(av.x, b3, acc[0][3]);
                acc[1][0] = fmaf(av.y, b0, acc[1][0]);
                acc[1][1] = fmaf(av.y, b1, acc[1][1]);
                acc[1][2] = fmaf(av.y, b2, acc[1][2]);
                acc[1][3] = fmaf(av.y, b3, acc[1][3]);
                acc[2][0] = fmaf(av.z, b0, acc[2][0]);
                acc[2][1] = fmaf(av.z, b1, acc[2][1]);
                acc[2][2] = fmaf(av.z, b2, acc[2][2]);
                acc[2][3] = fmaf(av.z, b3, acc[2][3]);
                acc[3][0] = fmaf(av.w, b0, acc[3][0]);
                acc[3][1] = fmaf(av.w, b1, acc[3][1]);
                acc[3][2] = fmaf(av.w, b2, acc[3][2]);
                acc[3][3] = fmaf(av.w, b3, acc[3][3]);
            }

            // stage prefetched tiles into the other buffer (conflict-free STS)
            if (has_next) {
                #pragma unroll
                for (int i = 0; i < 2; i++) {
                    int q = lkq + 4 * i;
                    As[buf ^ 1][q * 4 + 0][lr] = pfa[i].x;
                    As[buf ^ 1][q * 4 + 1][lr] = pfa[i].y;
                    As[buf ^ 1][q * 4 + 2][lr] = pfa[i].z;
                    As[buf ^ 1][q * 4 + 3][lr] = pfa[i].w;
                    Bs[buf ^ 1][q * 4 + 0][lr] = pfb[i].x;
                    Bs[buf ^ 1][q * 4 + 1][lr] = pfb[i].y;
                    Bs[buf ^ 1][q * 4 + 2][lr] = pfb[i].z;
                    Bs[buf ^ 1][q * 4 + 3][lr] = pfb[i].w;
                }
            }
            __syncthreads();
            buf ^= 1;
        }

        // fold: d = (x2 + c2) - 2*dot, matching the reference expression shape.
        #pragma unroll
        for (int j = 0; j < 4; j++) {
            const int col = n0 + tx + 16 * j;
            #pragma unroll
            for (int i = 0; i < 4; i++) {
                const int row = ty * 4 + i;
                float t = __fadd_rn(x2s[row], c2x[j]);
                float d = __fsub_rn(t, __fmul_rn(2.0f, acc[i][j]));
                if (d < bestd[i] || (d == bestd[i] && col < besti[i])) {
                    bestd[i] = d;
                    besti[i] = col;
                }
            }
        }
    }

    // ---- cross-thread argmin reduction (16 column-threads per row) ----------
    __syncthreads();
    #pragma unroll
    for (int i = 0; i < 4; i++) {
        redD[ty * 4 + i][tx] = bestd[i];
        redI[ty * 4 + i][tx] = besti[i];
    }
    __syncthreads();
    if (tid < BM) {
        float bd = redD[tid][0];
        int   bi = redI[tid][0];
        #pragma unroll
        for (int t = 1; t < 16; t++) {
            float d = redD[tid][t];
            int   ii = redI[tid][t];
            if (d < bd || (d == bd && ii < bi)) { bd = d; bi = ii; }
        }
        out[r0 + tid] = (float)bi;   // FLOAT32 output: store the index VALUE
    }
}

// ---------------------------------------------------------------------------
extern "C" void kernel_launch(void* const* d_in, const int* in_sizes, int n_in,
                              void* d_out, int out_size) {
    // x (N=32768 rows) is the larger buffer; vectors (K=8192) the smaller.
    const float* x;
    const float* vectors;
    if (n_in >= 2 && in_sizes[1] > in_sizes[0]) {
        x = (const float*)d_in[1];
        vectors = (const float*)d_in[0];
    } else {
        x = (const float*)d_in[0];
        vectors = (const float*)d_in[1];
    }
    float* out = (float*)d_out;

    vq_tiled<<<VQ_N / BM, NTHREADS>>>(x, vectors, out);
}

// round 17
// speedup vs baseline: 1.8011x; 1.8011x over previous
#include <cuda_runtime.h>
#include <cstdint>

// VectorQuantization: N=32768, K=8192, D=256 (reference-pinned).
// argmin_j ||x_i - c_j||^2 via d = (x2_i + c2_j) - 2 * (x_i . c_j).
// OUTPUT IS FLOAT32: store (float)index (round-14 root cause).
//
// Round-16 fix: norms kernels write the __device__ symbols g_c2/g_x2
// DIRECTLY (round 15 passed a __device__ symbol address from host code —
// ill-formed; the norms landed nowhere and vq_tiled read garbage).
//
// 128x128x16 tiling, 8x8 register tile (64 FMA per 4 LDS.128), c2/x2
// precomputed, 256 CTAs = one wave.

#define VQ_N 32768
#define VQ_K 8192
#define D_DIM 256
#define BM 128
#define BN 128
#define BK 16
#define NTHREADS 256
#define FLT_BIG 3.402823466e38f

__device__ float g_c2[VQ_K];
__device__ float g_x2[VQ_N];

// ---------------------------------------------------------------------------
// squared norms: one warp per row, fp64 accumulate, round once.
// Device symbols referenced INSIDE the kernels (no host-side symbol address).
// ---------------------------------------------------------------------------
__device__ __forceinline__ float row_norm2(const float* __restrict__ row, int lane) {
    double s = 0.0;
    for (int k = lane; k < D_DIM; k += 32) {
        float v = row[k];
        s += (double)v * (double)v;
    }
    #pragma unroll
    for (int off = 16; off > 0; off >>= 1)
        s += __shfl_down_sync(0xffffffffu, s, off);
    return (float)s;
}

__global__ void c2_kernel(const float* __restrict__ vectors) {
    int w = (blockIdx.x * blockDim.x + threadIdx.x) >> 5;
    int lane = threadIdx.x & 31;
    if (w >= VQ_K) return;
    float s = row_norm2(vectors + (size_t)w * D_DIM, lane);
    if (lane == 0) g_c2[w] = s;
}

__global__ void x2_kernel(const float* __restrict__ x) {
    int w = (blockIdx.x * blockDim.x + threadIdx.x) >> 5;
    int lane = threadIdx.x & 31;
    if (w >= VQ_N) return;
    float s = row_norm2(x + (size_t)w * D_DIM, lane);
    if (lane == 0) g_x2[w] = s;
}

// ---------------------------------------------------------------------------
// Main kernel. Static SMEM: tiles[2][2][16][128] = 32KB (+x2s 512B).
// Reduction buffers alias the tile storage after the main loop.
// ---------------------------------------------------------------------------
__global__ void __launch_bounds__(NTHREADS, 2)
vq_tiled(const float* __restrict__ x, const float* __restrict__ vectors,
         float* __restrict__ out) {
    __shared__ __align__(16) float tiles[2][2][BK][BM];   // [buf][A=0/B=1][k][row]
    __shared__ float x2s[BM];

    const int tid = threadIdx.x;
    const int tx = tid & 15;          // column group 0..15
    const int ty = tid >> 4;          // row group 0..15
    const int r0 = blockIdx.x * BM;

    // loader mapping: lr = row 0..127, lg = k-quad pair 0..1
    const int lr = tid & 127;
    const int lg = tid >> 7;

    // ---- x2 for this block's rows (precomputed) -----------------------------
    if (tid < BM) x2s[tid] = g_x2[r0 + tid];

    // ---- prologue: (chunk 0, kc 0) into buffer 0 ----------------------------
    {
        const float* ax = x + (size_t)(r0 + lr) * D_DIM;
        const float* bv = vectors + (size_t)lr * D_DIM;
        #pragma unroll
        for (int i = 0; i < 2; i++) {
            int q = lg * 2 + i;                       // k-quad 0..3 (16 k)
            float4 a = *reinterpret_cast<const float4*>(ax + q * 4);
            float4 b = *reinterpret_cast<const float4*>(bv + q * 4);
            tiles[0][0][q * 4 + 0][lr] = a.x;  tiles[0][0][q * 4 + 1][lr] = a.y;
            tiles[0][0][q * 4 + 2][lr] = a.z;  tiles[0][0][q * 4 + 3][lr] = a.w;
            tiles[0][1][q * 4 + 0][lr] = b.x;  tiles[0][1][q * 4 + 1][lr] = b.y;
            tiles[0][1][q * 4 + 2][lr] = b.z;  tiles[0][1][q * 4 + 3][lr] = b.w;
        }
    }
    __syncthreads();

    float bestd[8];
    int   besti[8];
    #pragma unroll
    for (int i = 0; i < 8; i++) { bestd[i] = FLT_BIG; besti[i] = 0; }

    const int nchunks = VQ_K / BN;    // 64
    const int nkc     = D_DIM / BK;   // 16
    int buf = 0;

    for (int chunk = 0; chunk < nchunks; chunk++) {
        const int n0 = chunk * BN;
        float acc[8][8];
        #pragma unroll
        for (int i = 0; i < 8; i++)
            #pragma unroll
            for (int j = 0; j < 8; j++) acc[i][j] = 0.f;

        for (int kc = 0; kc < nkc; kc++) {
            const bool has_next = (kc < nkc - 1) || (chunk < nchunks - 1);
            float4 pfa[2], pfb[2];

            if (has_next) {
                const int nc = (kc < nkc - 1) ? chunk : chunk + 1;
                const int nk = (kc < nkc - 1) ? kc + 1 : 0;
                const float* ax = x + (size_t)(r0 + lr) * D_DIM + nk * BK;
                const float* bv = vectors + (size_t)(nc * BN + lr) * D_DIM + nk * BK;
                #pragma unroll
                for (int i = 0; i < 2; i++) {
                    int q = lg * 2 + i;
                    pfa[i] = *reinterpret_cast<const float4*>(ax + q * 4);
                    pfb[i] = *reinterpret_cast<const float4*>(bv + q * 4);
                }
            }

            // 16 k-steps, 64 FMA each (8x8)
            #pragma unroll
            for (int k = 0; k < BK; k++) {
                float4 a0 = *reinterpret_cast<const float4*>(&tiles[buf][0][k][ty * 4]);
                float4 a1 = *reinterpret_cast<const float4*>(&tiles[buf][0][k][64 + ty * 4]);
                float4 b0 = *reinterpret_cast<const float4*>(&tiles[buf][1][k][tx * 4]);
                float4 b1 = *reinterpret_cast<const float4*>(&tiles[buf][1][k][64 + tx * 4]);
                float af[8] = {a0.x, a0.y, a0.z, a0.w, a1.x, a1.y, a1.z, a1.w};
                float bf[8] = {b0.x, b0.y, b0.z, b0.w, b1.x, b1.y, b1.z, b1.w};
                #pragma unroll
                for (int i = 0; i < 8; i++)
                    #pragma unroll
                    for (int j = 0; j < 8; j++)
                        acc[i][j] = fmaf(af[i], bf[j], acc[i][j]);
            }

            if (has_next) {
                #pragma unroll
                for (int i = 0; i < 2; i++) {
                    int q = lg * 2 + i;
                    tiles[buf ^ 1][0][q * 4 + 0][lr] = pfa[i].x;
                    tiles[buf ^ 1][0][q * 4 + 1][lr] = pfa[i].y;
                    tiles[buf ^ 1][0][q * 4 + 2][lr] = pfa[i].z;
                    tiles[buf ^ 1][0][q * 4 + 3][lr] = pfa[i].w;
                    tiles[buf ^ 1][1][q * 4 + 0][lr] = pfb[i].x;
                    tiles[buf ^ 1][1][q * 4 + 1][lr] = pfb[i].y;
                    tiles[buf ^ 1][1][q * 4 + 2][lr] = pfb[i].z;
                    tiles[buf ^ 1][1][q * 4 + 3][lr] = pfb[i].w;
                }
            }
            __syncthreads();
            buf ^= 1;
        }

        // fold: d = (x2 + c2) - 2*dot ; lexicographic (d, col) ties
        #pragma unroll
        for (int j = 0; j < 8; j++) {
            const int col = n0 + ((j < 4) ? (tx * 4 + j) : (64 + tx * 4 + j - 4));
            const float c2 = g_c2[col];
            #pragma unroll
            for (int i = 0; i < 8; i++) {
                const int ri = (i < 4) ? (ty * 4 + i) : (64 + ty * 4 + i - 4);
                float t = __fadd_rn(x2s[ri], c2);
                float d = __fsub_rn(t, __fmul_rn(2.0f, acc[i][j]));
                if (d < bestd[i] || (d == bestd[i] && col < besti[i])) {
                    bestd[i] = d;
                    besti[i] = col;
                }
            }
        }
    }

    // ---- cross-thread argmin reduction (alias tile smem; tiles are dead) ----
    __syncthreads();
    float (*redD)[16] = reinterpret_cast<float (*)[16]>(&tiles[0][0][0][0]);
    int   (*redI)[16] = reinterpret_cast<int (*)[16]>(
        reinterpret_cast<char*>(&tiles[0][0][0][0]) + BM * 16 * sizeof(float));

    #pragma unroll
    for (int i = 0; i < 8; i++) {
        const int ri = (i < 4) ? (ty * 4 + i) : (64 + ty * 4 + i - 4);
        redD[ri][tx] = bestd[i];
        redI[ri][tx] = besti[i];
    }
    __syncthreads();
    if (tid < BM) {
        float bd = redD[tid][0];
        int   bi = redI[tid][0];
        #pragma unroll
        for (int t = 1; t < 16; t++) {
            float d = redD[tid][t];
            int   ii = redI[tid][t];
            if (d < bd || (d == bd && ii < bi)) { bd = d; bi = ii; }
        }
        out[r0 + tid] = (float)bi;   // FLOAT32 output
    }
}

// ---------------------------------------------------------------------------
extern "C" void kernel_launch(void* const* d_in, const int* in_sizes, int n_in,
                              void* d_out, int out_size) {
    const float* x;
    const float* vectors;
    if (n_in >= 2 && in_sizes[1] > in_sizes[0]) {
        x = (const float*)d_in[1];
        vectors = (const float*)d_in[0];
    } else {
        x = (const float*)d_in[0];
        vectors = (const float*)d_in[1];
    }
    float* out = (float*)d_out;

    c2_kernel<<<(VQ_K * 32 + 255) / 256, 256>>>(vectors);
    x2_kernel<<<(VQ_N * 32 + 255) / 256, 256>>>(x);
    vq_tiled<<<VQ_N / BM, NTHREADS>>>(x, vectors, out);
}